// round 12
// baseline (speedup 1.0000x reference)
#include <cuda_runtime.h>
#include <math.h>

#define B_   2
#define T_   512
#define D_   512
#define NTOK (B_ * T_)       // 1024
#define NTOT (B_ * T_ * D_)  // 524288

// Per-token ||res_scaled||^2 contributions; every slot rewritten each call
// (plain stores -> no zero-init, no atomics, graph-replay safe).
__device__ double g_blocksum[NTOK];

__device__ __forceinline__ void fast_sincos(float x, float* s, float* c) {
    const float INV2PI = 0.15915494309189535f;
    float k = rintf(x * INV2PI);
    float y = fmaf(k, -6.2831855f, x);
    y = fmaf(k, 1.7484556e-7f, y);
    *s = __sinf(y);
    *c = __cosf(y);
}

// ---------------- K1: one token per block (1024 x 256) ----------------
__global__ __launch_bounds__(256) void token_kernel(
    const int*   __restrict__ token_ids,
    const float* __restrict__ resonances,
    const float* __restrict__ emb_scales,
    const float* __restrict__ emb_shifts,
    const float* __restrict__ emb_norm_p,
    const float* __restrict__ W_enc,      // [512,24]
    const float* __restrict__ b_enc,      // [24]
    const float* __restrict__ W_dec,      // [24,512]
    const float* __restrict__ b_dec,      // [512]
    const float* __restrict__ ecc_p,
    const float* __restrict__ ep_p,
    float*       __restrict__ out)        // [1024,512] <- res * scale_t (pre-global-norm)
{
    __shared__ float s_emb[D_];
    __shared__ float s_part[8][24];
    __shared__ float s_red[8];
    __shared__ float s_proj[24];
    __shared__ float s_latt[12];
    __shared__ float s_corr[24];
    __shared__ float s_s[4];             // f, e_in, e_in2, scale

    const int bt   = blockIdx.x;
    const int tid  = threadIdx.x;
    const int lane = tid & 31;
    const int wid  = tid >> 5;

    const float ecc      = ecc_p[0];
    const float ep       = ep_p[0];
    const float emb_norm = emb_norm_p[0];

    // ---- Phase A: embedding (2 dims/thread) + token norm ----
    const float tv   = (float)(token_ids[bt] % 1000000) * 1e-6f;
    const float base = tv + (float)(bt & (T_ - 1));

    float sn0, c0, sn1, c1;
    fast_sincos(resonances[tid]       * base, &sn0, &c0);
    fast_sincos(resonances[tid + 256] * base, &sn1, &c1);
    const float e0 = fmaf(c0 * (1.f + sn0) + sn0 * sn0, emb_scales[tid],       emb_shifts[tid]);
    const float e1 = fmaf(c1 * (1.f + sn1) + sn1 * sn1, emb_scales[tid + 256], emb_shifts[tid + 256]);
    s_emb[tid]       = e0;
    s_emb[tid + 256] = e1;
    float p = e0 * e0 + e1 * e1;
    #pragma unroll
    for (int o = 16; o; o >>= 1) p += __shfl_xor_sync(0xffffffffu, p, o);
    if (lane == 0) s_red[wid] = p;
    __syncthreads();
    if (tid < 32) {
        float v = (lane < 8) ? s_red[lane] : 0.f;
        #pragma unroll
        for (int o = 4; o; o >>= 1) v += __shfl_xor_sync(0xffffffffu, v, o);
        if (lane == 0) {
            const float tn = sqrtf(v);
            s_s[0] = (tn > 0.f) ? (emb_norm / tn) : 1.f;   // f
            s_s[1] = (tn > 0.f) ? emb_norm : tn;           // e_in
        }
    }
    __syncthreads();

    // ---- Phase B: enc matvec, warp-per-row-range, W_enc read coalesced (no transpose) ----
    if (lane < 24) {
        float pa = 0.f;
        const int dbase = wid * 64;
        #pragma unroll 8
        for (int i = 0; i < 64; i++) {
            const int d = dbase + i;
            pa = fmaf(s_emb[d], __ldg(&W_enc[d * 24 + lane]), pa);
        }
        s_part[wid][lane] = pa;
    }
    __syncthreads();
    if (tid < 24) {
        float acc = 0.f;
        #pragma unroll
        for (int w = 0; w < 8; w++) acc += s_part[w][tid];
        s_proj[tid] = fmaf(s_s[0], acc, b_enc[tid]);
    }
    __syncthreads();

    // ---- Phase B2: Golay encode/quantize/rescale/decode/threshold (warp 0) ----
    if (wid == 0) {
        const float e_in = s_s[1];
        float latt = 0.f;
        if (lane < 12) {
            float ge = s_proj[lane];
            #pragma unroll
            for (int j = 0; j < 11; j++)
                if ((lane + j) & 1) ge += s_proj[12 + j];
            if (lane & 1) ge += s_proj[23];
            latt = rintf(ge / ecc) * ecc;
        }
        float ls = latt * latt;
        #pragma unroll
        for (int o = 16; o; o >>= 1) ls += __shfl_xor_sync(0xffffffffu, ls, o);
        const float e_out  = sqrtf(ls);
        const float lscale = (e_in / (e_out + 1e-8f)) * ep;
        latt *= lscale;
        if (lane < 12) s_latt[lane] = latt;
        __syncwarp();
        if (lane < 24) {
            float gd;
            if (lane < 12) {
                gd = s_latt[lane];
            } else if (lane < 23) {
                const int j = lane - 12;
                gd = 0.f;
                #pragma unroll
                for (int kk = 0; kk < 12; kk++)
                    if ((kk + j) & 1) gd += s_latt[kk];
            } else {
                gd = s_latt[1] + s_latt[3] + s_latt[5] + s_latt[7] + s_latt[9] + s_latt[11];
            }
            s_corr[lane] = (fabsf(gd) > ecc) ? gd : 0.f;
        }
        if (lane == 0) s_s[2] = e_out * lscale;   // e_in2
    }
    __syncthreads();

    // ---- Phase C: res = corr @ W_dec + b_dec (2 dims/thread, W_dec L1-resident) ----
    float acc0 = __ldg(&b_dec[tid]);
    float acc1 = __ldg(&b_dec[tid + 256]);
    #pragma unroll
    for (int l = 0; l < 24; l++) {
        const float cl = s_corr[l];
        acc0 = fmaf(cl, __ldg(&W_dec[l * D_ + tid]),       acc0);
        acc1 = fmaf(cl, __ldg(&W_dec[l * D_ + tid + 256]), acc1);
    }
    float pr = acc0 * acc0 + acc1 * acc1;
    #pragma unroll
    for (int o = 16; o; o >>= 1) pr += __shfl_xor_sync(0xffffffffu, pr, o);
    if (lane == 0) s_red[wid] = pr;
    __syncthreads();
    if (tid < 32) {
        float v = (lane < 8) ? s_red[lane] : 0.f;
        #pragma unroll
        for (int o = 4; o; o >>= 1) v += __shfl_xor_sync(0xffffffffu, v, o);
        if (lane == 0) {
            const float e2 = sqrtf(fmaxf(v, 0.f));
            const float sc = s_s[2] / (e2 + 1e-8f) * ep;
            s_s[3] = sc;
            const double tn = (double)(sc * e2);
            g_blocksum[bt] = tn * tn;             // plain store; no atomic, no init
        }
    }
    __syncthreads();
    const float sc = s_s[3];
    out[bt * D_ + tid]       = acc0 * sc;
    out[bt * D_ + tid + 256] = acc1 * sc;
}

// ---------------- K2: out *= frac_norm * ||res||  (float4 RMW, 512 x 256) ----------------
__global__ __launch_bounds__(256) void scale_kernel(
    float4* __restrict__ out4, const float* __restrict__ frac_norm_p)
{
    __shared__ float s_m;
    const int i = blockIdx.x * blockDim.x + threadIdx.x;   // < NTOT/4
    float4 v = out4[i];   // issue load before waiting on the reduce
    // Warp 0 reduces the 1024 per-token contributions in a fixed order:
    // identical result in every block -> deterministic output.
    if (threadIdx.x < 32) {
        const int lane = threadIdx.x;
        double s = 0.0;
        #pragma unroll
        for (int j = 0; j < 32; j++) s += __ldcg(&g_blocksum[lane * 32 + j]);
        #pragma unroll
        for (int o = 16; o; o >>= 1) s += __shfl_xor_sync(0xffffffffu, s, o);
        if (lane == 0) s_m = frac_norm_p[0] * (float)sqrt(s);
    }
    __syncthreads();
    const float m = s_m;
    v.x *= m; v.y *= m; v.z *= m; v.w *= m;
    out4[i] = v;
}

extern "C" void kernel_launch(void* const* d_in, const int* in_sizes, int n_in,
                              void* d_out, int out_size)
{
    (void)in_sizes; (void)n_in; (void)out_size;
    const int*   token_ids  = (const int*)  d_in[0];
    const float* resonances = (const float*)d_in[1];
    const float* emb_scales = (const float*)d_in[2];
    const float* emb_shifts = (const float*)d_in[3];
    const float* emb_norm   = (const float*)d_in[4];
    // d_in[5] scale_weights, d_in[6] fractal_bias: cancel out of the output exactly
    const float* frac_norm  = (const float*)d_in[7];
    const float* W_enc      = (const float*)d_in[8];
    const float* b_enc      = (const float*)d_in[9];
    const float* W_dec      = (const float*)d_in[10];
    const float* b_dec      = (const float*)d_in[11];
    const float* ecc        = (const float*)d_in[12];
    const float* ep         = (const float*)d_in[13];
    float* out = (float*)d_out;

    token_kernel<<<NTOK, 256>>>(token_ids, resonances, emb_scales, emb_shifts,
                                emb_norm, W_enc, b_enc, W_dec, b_dec, ecc, ep, out);
    scale_kernel<<<NTOT / 4 / 256, 256>>>((float4*)out, frac_norm);
}

// round 16
// speedup vs baseline: 1.3349x; 1.3349x over previous
#include <cuda_runtime.h>
#include <math.h>

#define B_   2
#define T_   512
#define D_   512
#define NTOK (B_ * T_)       // 1024
#define NTOT (B_ * T_ * D_)  // 524288

// Per-token scratch; every slot rewritten every call (plain stores ->
// no zero-init, no atomics, graph-replay safe).
__device__ float g_blocksum[NTOK];   // (scale_t * ||res_raw||)^2 per token
__device__ float g_corr[NTOK * 24];  // corrected Golay vector per token
__device__ float g_scale[NTOK];      // per-token output scale

__device__ __forceinline__ void fast_sincos(float x, float* s, float* c) {
    const float INV2PI = 0.15915494309189535f;
    float k = rintf(x * INV2PI);
    float y = fmaf(k, -6.2831855f, x);
    y = fmaf(k, 1.7484556e-7f, y);
    *s = __sinf(y);
    *c = __cosf(y);
}

// ---------------- K1: one token per block (1024 x 256), scalars only ----------------
__global__ __launch_bounds__(256) void token_kernel(
    const int*   __restrict__ token_ids,
    const float* __restrict__ resonances,
    const float* __restrict__ emb_scales,
    const float* __restrict__ emb_shifts,
    const float* __restrict__ emb_norm_p,
    const float* __restrict__ W_enc,      // [512,24]
    const float* __restrict__ b_enc,      // [24]
    const float* __restrict__ W_dec,      // [24,512]
    const float* __restrict__ b_dec,      // [512]
    const float* __restrict__ ecc_p,
    const float* __restrict__ ep_p)
{
    __shared__ float s_emb[D_];
    __shared__ float s_part[8][24];
    __shared__ float s_red[8];
    __shared__ float s_proj[24];
    __shared__ float s_latt[12];
    __shared__ float s_corr[24];
    __shared__ float s_s[4];             // f, e_in, e_in2, -

    const int bt   = blockIdx.x;
    const int tid  = threadIdx.x;
    const int lane = tid & 31;
    const int wid  = tid >> 5;

    const float ecc      = ecc_p[0];
    const float ep       = ep_p[0];
    const float emb_norm = emb_norm_p[0];

    // ---- Phase A: embedding (2 dims/thread) + token norm ----
    const float tv   = (float)(token_ids[bt] % 1000000) * 1e-6f;
    const float base = tv + (float)(bt & (T_ - 1));

    float sn0, c0, sn1, c1;
    fast_sincos(resonances[tid]       * base, &sn0, &c0);
    fast_sincos(resonances[tid + 256] * base, &sn1, &c1);
    const float e0 = fmaf(c0 * (1.f + sn0) + sn0 * sn0, emb_scales[tid],       emb_shifts[tid]);
    const float e1 = fmaf(c1 * (1.f + sn1) + sn1 * sn1, emb_scales[tid + 256], emb_shifts[tid + 256]);
    s_emb[tid]       = e0;
    s_emb[tid + 256] = e1;
    float p = e0 * e0 + e1 * e1;
    #pragma unroll
    for (int o = 16; o; o >>= 1) p += __shfl_xor_sync(0xffffffffu, p, o);
    if (lane == 0) s_red[wid] = p;
    __syncthreads();
    if (tid < 32) {
        float v = (lane < 8) ? s_red[lane] : 0.f;
        #pragma unroll
        for (int o = 4; o; o >>= 1) v += __shfl_xor_sync(0xffffffffu, v, o);
        if (lane == 0) {
            const float tn = sqrtf(v);
            s_s[0] = (tn > 0.f) ? (emb_norm / tn) : 1.f;   // f
            s_s[1] = (tn > 0.f) ? emb_norm : tn;           // e_in
        }
    }
    __syncthreads();

    // ---- Phase B: enc matvec, warp-per-row-range, 2 accumulators ----
    if (lane < 24) {
        float pa = 0.f, pb = 0.f;
        const int dbase = wid * 64;
        #pragma unroll 8
        for (int i = 0; i < 64; i += 2) {
            pa = fmaf(s_emb[dbase + i],     __ldg(&W_enc[(dbase + i)     * 24 + lane]), pa);
            pb = fmaf(s_emb[dbase + i + 1], __ldg(&W_enc[(dbase + i + 1) * 24 + lane]), pb);
        }
        s_part[wid][lane] = pa + pb;
    }
    __syncthreads();
    if (tid < 24) {
        float acc = 0.f;
        #pragma unroll
        for (int w = 0; w < 8; w++) acc += s_part[w][tid];
        s_proj[tid] = fmaf(s_s[0], acc, b_enc[tid]);
    }
    __syncthreads();

    // ---- Phase B2: Golay encode/quantize/rescale/decode/threshold (warp 0) ----
    if (wid == 0) {
        const float e_in = s_s[1];
        float latt = 0.f;
        if (lane < 12) {
            float ge = s_proj[lane];
            #pragma unroll
            for (int j = 0; j < 11; j++)
                if ((lane + j) & 1) ge += s_proj[12 + j];
            if (lane & 1) ge += s_proj[23];
            latt = rintf(ge / ecc) * ecc;
        }
        float ls = latt * latt;
        #pragma unroll
        for (int o = 16; o; o >>= 1) ls += __shfl_xor_sync(0xffffffffu, ls, o);
        const float e_out  = sqrtf(ls);
        const float lscale = (e_in / (e_out + 1e-8f)) * ep;
        latt *= lscale;
        if (lane < 12) s_latt[lane] = latt;
        __syncwarp();
        if (lane < 24) {
            float gd;
            if (lane < 12) {
                gd = s_latt[lane];
            } else if (lane < 23) {
                const int j = lane - 12;
                gd = 0.f;
                #pragma unroll
                for (int kk = 0; kk < 12; kk++)
                    if ((kk + j) & 1) gd += s_latt[kk];
            } else {
                gd = s_latt[1] + s_latt[3] + s_latt[5] + s_latt[7] + s_latt[9] + s_latt[11];
            }
            const float cr = (fabsf(gd) > ecc) ? gd : 0.f;
            s_corr[lane] = cr;
            g_corr[bt * 24 + lane] = cr;           // for K2's recompute
        }
        if (lane == 0) s_s[2] = e_out * lscale;    // e_in2
    }
    __syncthreads();

    // ---- Phase C: raw dec norm only (no out store) ----
    float acc0 = __ldg(&b_dec[tid]);
    float acc1 = __ldg(&b_dec[tid + 256]);
    #pragma unroll
    for (int l = 0; l < 24; l++) {
        const float cl = s_corr[l];
        acc0 = fmaf(cl, __ldg(&W_dec[l * D_ + tid]),       acc0);
        acc1 = fmaf(cl, __ldg(&W_dec[l * D_ + tid + 256]), acc1);
    }
    float pr = acc0 * acc0 + acc1 * acc1;
    #pragma unroll
    for (int o = 16; o; o >>= 1) pr += __shfl_xor_sync(0xffffffffu, pr, o);
    if (lane == 0) s_red[wid] = pr;
    __syncthreads();
    if (tid == 0) {
        float v = 0.f;
        #pragma unroll
        for (int w = 0; w < 8; w++) v += s_red[w];
        const float e2 = sqrtf(fmaxf(v, 0.f));
        const float sc = s_s[2] / (e2 + 1e-8f) * ep;
        g_scale[bt] = sc;
        const float tn = sc * e2;
        g_blocksum[bt] = tn * tn;                  // plain store; no atomic, no init
    }
}

// ---------------- K2: write-only output (1024 x 256) ----------------
// out[bt] = (g_corr[bt] @ W_dec + b_dec) * g_scale[bt] * frac_norm * sqrt(sum g_blocksum)
__global__ __launch_bounds__(256) void out_kernel(
    const float* __restrict__ W_dec,      // [24,512]
    const float* __restrict__ b_dec,      // [512]
    const float* __restrict__ frac_norm_p,
    float*       __restrict__ out)        // [1024,512]
{
    __shared__ float s_c[24];
    __shared__ float s_red[8];
    __shared__ float s_m;

    const int bt   = blockIdx.x;
    const int tid  = threadIdx.x;
    const int lane = tid & 31;
    const int wid  = tid >> 5;

    // Parallel fixed-order reduce of 1024 float contributions (identical
    // order in every block -> bitwise-identical m everywhere).
    {
        const float4 v4 = __ldcg(&((const float4*)g_blocksum)[tid]);   // 256 x float4
        float v = ((v4.x + v4.y) + (v4.z + v4.w));
        #pragma unroll
        for (int o = 16; o; o >>= 1) v += __shfl_xor_sync(0xffffffffu, v, o);
        if (lane == 0) s_red[wid] = v;
    }
    if (tid < 24) s_c[tid] = g_corr[bt * 24 + tid];
    __syncthreads();
    if (tid == 0) {
        float s = 0.f;
        #pragma unroll
        for (int w = 0; w < 8; w++) s += s_red[w];
        s_m = g_scale[bt] * frac_norm_p[0] * sqrtf(s);
    }
    __syncthreads();
    const float m = s_m;

    float acc0 = __ldg(&b_dec[tid]);
    float acc1 = __ldg(&b_dec[tid + 256]);
    #pragma unroll
    for (int l = 0; l < 24; l++) {
        const float cl = s_c[l];
        acc0 = fmaf(cl, __ldg(&W_dec[l * D_ + tid]),       acc0);
        acc1 = fmaf(cl, __ldg(&W_dec[l * D_ + tid + 256]), acc1);
    }
    out[bt * D_ + tid]       = acc0 * m;
    out[bt * D_ + tid + 256] = acc1 * m;
}

extern "C" void kernel_launch(void* const* d_in, const int* in_sizes, int n_in,
                              void* d_out, int out_size)
{
    (void)in_sizes; (void)n_in; (void)out_size;
    const int*   token_ids  = (const int*)  d_in[0];
    const float* resonances = (const float*)d_in[1];
    const float* emb_scales = (const float*)d_in[2];
    const float* emb_shifts = (const float*)d_in[3];
    const float* emb_norm   = (const float*)d_in[4];
    // d_in[5] scale_weights, d_in[6] fractal_bias: cancel out of the output exactly
    const float* frac_norm  = (const float*)d_in[7];
    const float* W_enc      = (const float*)d_in[8];
    const float* b_enc      = (const float*)d_in[9];
    const float* W_dec      = (const float*)d_in[10];
    const float* b_dec      = (const float*)d_in[11];
    const float* ecc        = (const float*)d_in[12];
    const float* ep         = (const float*)d_in[13];
    float* out = (float*)d_out;

    token_kernel<<<NTOK, 256>>>(token_ids, resonances, emb_scales, emb_shifts,
                                emb_norm, W_enc, b_enc, W_dec, b_dec, ecc, ep);
    out_kernel<<<NTOK, 256>>>(W_dec, b_dec, frac_norm, out);
}